// round 2
// baseline (speedup 1.0000x reference)
#include <cuda_runtime.h>
#include <math.h>

#define Bb 32
#define Hh 1024
#define Ss 512
#define Tt 32
#define N3 3072
#define NN 6144
#define KCH 128
#define KSPLIT 8
#define NT 128
#define NBLK (NN / NT)   // 48

// ---------------- device scratch ----------------
__device__ __align__(16) float g_wt[(size_t)Hh * NN];     // [k][n] transposed combined weights (w_ih | w_hh)
__device__ __align__(16) float g_bias[NN];                // (b_ih | b_hh)
__device__ __align__(16) float g_h[Bb * Hh];              // GRU hidden
__device__ __align__(16) float g_x[Bb * Hh];              // decoder input
__device__ __align__(16) float g_a[Bb * Ss];              // inputs . v2
__device__ __align__(16) float g_v1[Hh];                  // W1^T V
__device__ __align__(16) float g_v2[Hh];                  // W2^T V
__device__ __align__(16) float g_gbuf[(size_t)KSPLIT * Bb * NN]; // GEMM partials

// ---------------- prep kernels ----------------
__global__ void prep_init(const float* __restrict__ features) {
    int i = blockIdx.x * 1024 + threadIdx.x;
    g_h[i] = 0.f;
    g_x[i] = features[i];
}

// v1[d] = sum_h V[h]*W1[h,d] ; v2 with W2
__global__ void prep_v(const float* __restrict__ W1, const float* __restrict__ W2,
                       const float* __restrict__ V) {
    __shared__ float vs[Hh];
    int tid = threadIdx.x;
    for (int i = tid; i < Hh; i += 256) vs[i] = V[i];
    __syncthreads();
    int sel = blockIdx.x >> 2;          // 0 -> W1/v1, 1 -> W2/v2
    int d = (blockIdx.x & 3) * 256 + tid;
    const float* W = sel ? W2 : W1;
    float acc = 0.f;
    for (int h = 0; h < Hh; h++) acc = fmaf(vs[h], W[(size_t)h * Hh + d], acc);
    if (sel) g_v2[d] = acc; else g_v1[d] = acc;
}

// transpose weights into g_wt[k][n]; n<3072 -> w_ih, else w_hh
__global__ void prep_wt(const float* __restrict__ w_ih, const float* __restrict__ w_hh) {
    __shared__ float tile[32][33];
    int nb = blockIdx.x;   // NN/32 = 192
    int kb = blockIdx.y;   // H/32 = 32
    int tx = threadIdx.x;  // 32
    int ty = threadIdx.y;  // 8
    for (int i = ty; i < 32; i += 8) {
        int n = nb * 32 + i;
        int k = kb * 32 + tx;
        tile[i][tx] = (n < N3) ? w_ih[(size_t)n * Hh + k]
                               : w_hh[(size_t)(n - N3) * Hh + k];
    }
    __syncthreads();
    for (int i = ty; i < 32; i += 8) {
        int k = kb * 32 + i;
        int n = nb * 32 + tx;
        g_wt[(size_t)k * NN + n] = tile[tx][i];
    }
}

__global__ void prep_bias(const float* __restrict__ b_ih, const float* __restrict__ b_hh) {
    int i = blockIdx.x * 1024 + threadIdx.x;
    g_bias[i] = (i < N3) ? b_ih[i] : b_hh[i - N3];
}

// a[row] = inputs[row,:] . v2   (row = b*S + s), one warp per row
__global__ void prep_a(const float* __restrict__ inputs) {
    __shared__ float v2s[Hh];
    int tid = threadIdx.x;
    for (int i = tid; i < Hh; i += 256) v2s[i] = g_v2[i];
    __syncthreads();
    int warp = tid >> 5, lane = tid & 31;
    int row = blockIdx.x * 8 + warp;
    const float* r = inputs + (size_t)row * Hh;
    float acc = 0.f;
#pragma unroll
    for (int i = 0; i < 8; i++) {
        float4 x4 = *(const float4*)&r[(i * 32 + lane) * 4];
        float4 v4 = *(const float4*)&v2s[(i * 32 + lane) * 4];
        acc += x4.x * v4.x + x4.y * v4.y + x4.z * v4.z + x4.w * v4.w;
    }
#pragma unroll
    for (int o = 16; o > 0; o >>= 1) acc += __shfl_xor_sync(0xFFFFFFFFu, acc, o);
    if (lane == 0) g_a[row] = acc;
}

// ---------------- per-step GEMM: y[b,n] = A[b,:] . g_wt[:,n] (K-split partials) ----------------
// A = g_x for n<3072 (gi), g_h for n>=3072 (gh)
__global__ void __launch_bounds__(256) gru_gemm() {
    __shared__ __align__(16) float As[KCH][36];
    __shared__ __align__(16) float Ws[8][128];
    const int nb = blockIdx.x;
    const int kz = blockIdx.y;
    const int n0 = nb * NT;
    const int k0 = kz * KCH;
    const float* Ag = (n0 < N3) ? g_x : g_h;
    const int tid = threadIdx.x;
    const int tx = tid & 31;
    const int ty = tid >> 5;
    const int b0 = ty * 4;

    // stage A chunk transposed: As[k][b]
#pragma unroll
    for (int i = 0; i < (Bb * KCH) / 256; i++) {
        int idx = tid + i * 256;
        int bb = idx >> 7;       // KCH = 128
        int kk = idx & 127;
        As[kk][bb] = Ag[bb * Hh + k0 + kk];
    }

    float acc[4][4];
#pragma unroll
    for (int i = 0; i < 4; i++)
#pragma unroll
        for (int j = 0; j < 4; j++) acc[i][j] = 0.f;

    const int wkk = tid >> 5;
    const int wn4 = (tid & 31) * 4;

    for (int k8 = 0; k8 < KCH / 8; k8++) {
        __syncthreads();
        *(float4*)&Ws[wkk][wn4] =
            *(const float4*)&g_wt[(size_t)(k0 + k8 * 8 + wkk) * NN + n0 + wn4];
        __syncthreads();
#pragma unroll
        for (int kk = 0; kk < 8; kk++) {
            const float4 a4 = *(const float4*)&As[k8 * 8 + kk][b0];
            const float4 w4 = *(const float4*)&Ws[kk][tx * 4];
            float av[4] = {a4.x, a4.y, a4.z, a4.w};
#pragma unroll
            for (int i = 0; i < 4; i++) {
                acc[i][0] = fmaf(av[i], w4.x, acc[i][0]);
                acc[i][1] = fmaf(av[i], w4.y, acc[i][1]);
                acc[i][2] = fmaf(av[i], w4.z, acc[i][2]);
                acc[i][3] = fmaf(av[i], w4.w, acc[i][3]);
            }
        }
    }
#pragma unroll
    for (int i = 0; i < 4; i++) {
        float4 o = make_float4(acc[i][0], acc[i][1], acc[i][2], acc[i][3]);
        *(float4*)&g_gbuf[((size_t)(kz * Bb) + b0 + i) * NN + n0 + tx * 4] = o;
    }
}

// ---------------- per-step combine + score + argmax + gather ----------------
__global__ void __launch_bounds__(1024) gru_step(const float* __restrict__ inputs,
                                                 const float* __restrict__ mask,
                                                 float* __restrict__ probs, int t) {
    const int b = blockIdx.x;
    const int j = threadIdx.x;
    __shared__ float red[1024];
    __shared__ float sv[512];
    __shared__ int si[512];

    float gr = g_bias[j],        gz = g_bias[j + 1024], gn = g_bias[j + 2048];
    float hr = g_bias[j + 3072], hz = g_bias[j + 4096], hn = g_bias[j + 5120];
#pragma unroll
    for (int kz = 0; kz < KSPLIT; kz++) {
        const float* gb = g_gbuf + ((size_t)(kz * Bb) + b) * NN;
        gr += gb[j];        gz += gb[j + 1024]; gn += gb[j + 2048];
        hr += gb[j + 3072]; hz += gb[j + 4096]; hn += gb[j + 5120];
    }
    float hold = g_h[b * Hh + j];
    float r = 1.f / (1.f + expf(-(gr + hr)));
    float z = 1.f / (1.f + expf(-(gz + hz)));
    float nv = tanhf(gn + r * hn);
    float hnew = (1.f - z) * nv + z * hold;
    g_h[b * Hh + j] = hnew;

    // c = v1 . h_new
    red[j] = g_v1[j] * hnew;
    __syncthreads();
    for (int st = 512; st >= 1; st >>= 1) {
        if (j < st) red[j] += red[j + st];
        __syncthreads();
    }
    float c = red[0];

    // scores + argmax(scores+mask)
    if (j < Ss) {
        float sc = tanhf(c + g_a[b * Ss + j]);
        probs[((size_t)b * Tt + t) * Ss + j] = sc;
        sv[j] = sc + mask[b * Ss + j];
        si[j] = j;
    }
    __syncthreads();
    for (int st = 256; st >= 1; st >>= 1) {
        if (j < st) {
            float v = sv[j + st]; int ii = si[j + st];
            if (v > sv[j] || (v == sv[j] && ii < si[j])) { sv[j] = v; si[j] = ii; }
        }
        __syncthreads();
    }
    int idx = si[0];
    // gather next decoder input
    g_x[b * Hh + j] = inputs[((size_t)b * Ss + idx) * Hh + j];
}

// ---------------- context from step-0 scores ----------------
__global__ void __launch_bounds__(256) ctx_kernel(const float* __restrict__ inputs,
                                                  const float* __restrict__ mask,
                                                  const float* __restrict__ probs,
                                                  float* __restrict__ ctx) {
    const int b = blockIdx.x;
    const int hq = blockIdx.y;
    const int tid = threadIdx.x;
    __shared__ float p[Ss];
    __shared__ float red[256];

    for (int s = tid; s < Ss; s += 256)
        p[s] = probs[(size_t)b * Tt * Ss + s] + mask[b * Ss + s];
    __syncthreads();
    float m = -1e30f;
    for (int s = tid; s < Ss; s += 256) m = fmaxf(m, p[s]);
    red[tid] = m;
    __syncthreads();
    for (int st = 128; st >= 1; st >>= 1) {
        if (tid < st) red[tid] = fmaxf(red[tid], red[tid + st]);
        __syncthreads();
    }
    const float mx = red[0];
    __syncthreads();
    float sm = 0.f;
    for (int s = tid; s < Ss; s += 256) {
        float e = expf(p[s] - mx);
        p[s] = e;
        sm += e;
    }
    red[tid] = sm;
    __syncthreads();
    for (int st = 128; st >= 1; st >>= 1) {
        if (tid < st) red[tid] += red[tid + st];
        __syncthreads();
    }
    const float Z = red[0];
    __syncthreads();
    const int h = hq * 256 + tid;
    float acc = 0.f;
    for (int s = 0; s < Ss; s++)
        acc = fmaf(p[s], inputs[((size_t)b * Ss + s) * Hh + h], acc);
    ctx[b * Hh + h] = acc / Z;
}

// ---------------- launch ----------------
extern "C" void kernel_launch(void* const* d_in, const int* in_sizes, int n_in,
                              void* d_out, int out_size) {
    const float* inputs   = (const float*)d_in[0];
    const float* mask     = (const float*)d_in[1];
    // d_in[2] = inputs_embeds, unused (use_emb=False path)
    const float* features = (const float*)d_in[3];
    const float* w_ih     = (const float*)d_in[4];
    const float* b_ih     = (const float*)d_in[5];
    const float* w_hh     = (const float*)d_in[6];
    const float* b_hh     = (const float*)d_in[7];
    const float* W1       = (const float*)d_in[8];
    const float* W2       = (const float*)d_in[9];
    const float* V        = (const float*)d_in[10];

    float* out   = (float*)d_out;
    float* probs = out;                            // [B, T, S]
    float* ctx   = out + (size_t)Bb * Tt * Ss;     // [B, H]

    prep_init<<<Bb, 1024>>>(features);
    prep_v<<<8, 256>>>(W1, W2, V);
    prep_wt<<<dim3(NN / 32, Hh / 32), dim3(32, 8)>>>(w_ih, w_hh);
    prep_bias<<<NN / 1024, 1024>>>(b_ih, b_hh);
    prep_a<<<(Bb * Ss) / 8, 256>>>(inputs);

    for (int t = 0; t < Tt; t++) {
        gru_gemm<<<dim3(NBLK, KSPLIT), 256>>>();
        gru_step<<<Bb, 1024>>>(inputs, mask, probs, t);
    }
    ctx_kernel<<<dim3(Bb, 4), 256>>>(inputs, mask, probs, ctx);
}

// round 4
// speedup vs baseline: 1.2835x; 1.2835x over previous
#include <cuda_runtime.h>
#include <cuda_bf16.h>
#include <cstdint>
#include <math.h>

#define Bb 32
#define Hh 1024
#define Ss 512
#define Tt 32
#define N3 3072
#define NN 6144
#define NCTA 96          // 48 row-tiles x 2 K-splits
#define DSMEM 65536      // B block: [prec 2][kc 32][nn 4][lane 32] x 8B

// ===================== helpers =====================
__device__ __forceinline__ uint32_t pack_bf(__nv_bfloat16 x, __nv_bfloat16 y) {
    return (uint32_t)__bfloat16_as_ushort(x) | ((uint32_t)__bfloat16_as_ushort(y) << 16);
}
__device__ __forceinline__ void bsplit(float v, __nv_bfloat16& hi, __nv_bfloat16& lo) {
    hi = __float2bfloat16(v);
    lo = __float2bfloat16(v - __bfloat162float(hi));
}
// mma.sync m16n8k16 row.col bf16 -> f32
__device__ __forceinline__ void mma16816(float* c, const uint32_t* a, uint32_t b0, uint32_t b1) {
    asm volatile(
        "mma.sync.aligned.m16n8k16.row.col.f32.bf16.bf16.f32 "
        "{%0,%1,%2,%3}, {%4,%5,%6,%7}, {%8,%9}, {%0,%1,%2,%3};"
        : "+f"(c[0]), "+f"(c[1]), "+f"(c[2]), "+f"(c[3])
        : "r"(a[0]), "r"(a[1]), "r"(a[2]), "r"(a[3]), "r"(b0), "r"(b1));
}
// B-fragment byte offset (within one 32KB prec block) for element (k=j%512, n=b)
__device__ __forceinline__ uint32_t bfr_off(int j, int b, int& kz) {
    kz = j >> 9;
    int kk = j & 511;
    int kc = kk >> 4, r = kk & 15;
    int nn = b >> 3, g = b & 7, t = (r & 7) >> 1;
    return (uint32_t)(kc * 1024 + nn * 256 + (g * 4 + t) * 8 + ((r >= 8) ? 4 : 0) + (r & 1) * 2);
}

// ===================== device scratch =====================
// A fragments: [nt 48][kz 2][w 8][kc 32][lane 32] of uint4 (a0..a3), hi & lo
__device__ __align__(128) uint4 g_wfrh[786432];
__device__ __align__(128) uint4 g_wfrl[786432];
// B fragments: [side 2 (x|h)][kz 2][prec 2][kc 32][nn 4][lane 32] x 8B = 256KB
__device__ __align__(128) char g_bfr[262144];
// y transposed: [kz 2][batch 32][gate 6144] f32
__device__ __align__(16) float g_yT[(size_t)2 * Bb * NN];
__device__ __align__(16) float g_h[Bb * Hh];
__device__ __align__(16) float g_a[Bb * Ss];
__device__ __align__(16) float g_v1[Hh];
__device__ __align__(16) float g_v2[Hh];
__device__ __align__(16) float g_bias[NN];
__device__ unsigned g_barcnt;

// ===================== prep kernels =====================
// pack weights in A-fragment order, bf16 hi/lo
__global__ void prep_wfr(const float* __restrict__ w_ih, const float* __restrict__ w_hh) {
    int idx = blockIdx.x * 256 + threadIdx.x;      // 0..786431
    int lane = idx & 31;
    int kc = (idx >> 5) & 31;
    int w = (idx >> 10) & 7;
    int kz = (idx >> 13) & 1;
    int nt = idx >> 14;
    int g = lane >> 2, t = lane & 3;
    int r0 = nt * 128 + w * 16 + g;
    int r1 = r0 + 8;
    int k0 = kz * 512 + kc * 16 + 2 * t;

    float v[8];
    int rows[2] = {r0, r1};
#pragma unroll
    for (int rr = 0; rr < 2; rr++) {
        const float* W = (rows[rr] < N3) ? (w_ih + (size_t)rows[rr] * Hh)
                                         : (w_hh + (size_t)(rows[rr] - N3) * Hh);
        v[rr * 2 + 0] = W[k0];
        v[rr * 2 + 1] = W[k0 + 1];
        v[rr * 2 + 4] = W[k0 + 8];
        v[rr * 2 + 5] = W[k0 + 9];
    }
    uint32_t hi[4], lo[4];
#pragma unroll
    for (int i = 0; i < 4; i++) {
        __nv_bfloat16 h0, l0, h1, l1;
        bsplit(v[2 * i], h0, l0);
        bsplit(v[2 * i + 1], h1, l1);
        hi[i] = pack_bf(h0, h1);
        lo[i] = pack_bf(l0, l1);
    }
    g_wfrh[idx] = make_uint4(hi[0], hi[1], hi[2], hi[3]);
    g_wfrl[idx] = make_uint4(lo[0], lo[1], lo[2], lo[3]);
}

// initial B pack: x = features (hi/lo), h = 0; also zero g_h and reset barrier
__global__ void prep_pack_b(const float* __restrict__ features) {
    int b = blockIdx.x, tid = threadIdx.x;
    if (b == 0 && tid == 0) g_barcnt = 0u;
#pragma unroll
    for (int jj = 0; jj < 4; jj++) {
        int j = tid + jj * 256;
        float v = features[b * Hh + j];
        __nv_bfloat16 hi, lo;
        bsplit(v, hi, lo);
        int kz;
        uint32_t off = bfr_off(j, b, kz);
        char* px = g_bfr + kz * 65536;
        *(unsigned short*)(px + off) = __bfloat16_as_ushort(hi);
        *(unsigned short*)(px + 32768 + off) = __bfloat16_as_ushort(lo);
        char* ph = g_bfr + 131072 + kz * 65536;
        *(unsigned short*)(ph + off) = 0;
        *(unsigned short*)(ph + 32768 + off) = 0;
        g_h[b * Hh + j] = 0.f;
    }
}

__global__ void prep_v(const float* __restrict__ W1, const float* __restrict__ W2,
                       const float* __restrict__ V) {
    __shared__ float vs[Hh];
    int tid = threadIdx.x;
    for (int i = tid; i < Hh; i += 256) vs[i] = V[i];
    __syncthreads();
    int sel = blockIdx.x >> 2;
    int d = (blockIdx.x & 3) * 256 + tid;
    const float* W = sel ? W2 : W1;
    float acc = 0.f;
    for (int h = 0; h < Hh; h++) acc = fmaf(vs[h], W[(size_t)h * Hh + d], acc);
    if (sel) g_v2[d] = acc; else g_v1[d] = acc;
}

__global__ void prep_bias(const float* __restrict__ b_ih, const float* __restrict__ b_hh) {
    int i = blockIdx.x * 1024 + threadIdx.x;
    g_bias[i] = (i < N3) ? b_ih[i] : b_hh[i - N3];
}

__global__ void prep_a(const float* __restrict__ inputs) {
    __shared__ float v2s[Hh];
    int tid = threadIdx.x;
    for (int i = tid; i < Hh; i += 256) v2s[i] = g_v2[i];
    __syncthreads();
    int warp = tid >> 5, lane = tid & 31;
    int row = blockIdx.x * 8 + warp;
    const float* r = inputs + (size_t)row * Hh;
    float acc = 0.f;
#pragma unroll
    for (int i = 0; i < 8; i++) {
        float4 x4 = *(const float4*)&r[(i * 32 + lane) * 4];
        float4 v4 = *(const float4*)&v2s[(i * 32 + lane) * 4];
        acc += x4.x * v4.x + x4.y * v4.y + x4.z * v4.z + x4.w * v4.w;
    }
#pragma unroll
    for (int o = 16; o > 0; o >>= 1) acc += __shfl_xor_sync(0xFFFFFFFFu, acc, o);
    if (lane == 0) g_a[row] = acc;
}

// ===================== persistent GRU loop =====================
__device__ __forceinline__ void grid_bar(unsigned target) {
    __syncthreads();
    if (threadIdx.x == 0) {
        __threadfence();
        atomicAdd(&g_barcnt, 1u);
        while (atomicAdd(&g_barcnt, 0u) < target) {}
        __threadfence();
    }
    __syncthreads();
}

extern __shared__ char dsm[];

__global__ void __launch_bounds__(256, 1)
gru_persist(const float* __restrict__ inputs, const float* __restrict__ mask,
            float* __restrict__ probs) {
    const int c = blockIdx.x;           // 0..95
    const int nt = c >> 1;              // row tile 0..47
    const int kz = c & 1;               // K-split half
    const int tid = threadIdx.x;
    const int wid = tid >> 5;
    const int lane = tid & 31;
    const int side = (nt >= 24) ? 1 : 0; // x-side for gate rows < 3072, else h-side
    const int b = c;                     // epilogue batch (c < 32 only)

    const uint4* Ah = g_wfrh + (((size_t)nt * 2 + kz) * 8 + wid) * 1024;
    const uint4* Al = g_wfrl + (((size_t)nt * 2 + kz) * 8 + wid) * 1024;
    const char* bsrc = g_bfr + side * 131072 + kz * 65536;

    float* red = (float*)dsm;
    float* sv = (float*)(dsm + 1024);
    int* si = (int*)(dsm + 3072);

    for (int t = 0; t < Tt; t++) {
        // ---- stage B block (64KB: hi 32KB | lo 32KB) into smem ----
        {
            const uint4* s = (const uint4*)bsrc;
            uint4* d = (uint4*)dsm;
#pragma unroll 4
            for (int i = tid; i < 4096; i += 256) d[i] = s[i];
        }
        __syncthreads();

        // ---- GEMM: 128 rows x 32 batch x K=512, 3-term bf16 split ----
        float acc[4][4];
#pragma unroll
        for (int i = 0; i < 4; i++)
#pragma unroll
            for (int j = 0; j < 4; j++) acc[i][j] = 0.f;

#pragma unroll 2
        for (int kc = 0; kc < 32; kc++) {
            uint4 ah = Ah[kc * 32 + lane];
            uint4 al = Al[kc * 32 + lane];
            const char* bb = dsm + kc * 1024 + lane * 8;
#pragma unroll
            for (int nn = 0; nn < 4; nn++) {
                uint2 bh = *(const uint2*)(bb + nn * 256);
                uint2 bl = *(const uint2*)(bb + 32768 + nn * 256);
                mma16816(acc[nn], &ah.x, bh.x, bh.y);
                mma16816(acc[nn], &ah.x, bl.x, bl.y);
                mma16816(acc[nn], &al.x, bh.x, bh.y);
            }
        }

        // ---- store y transposed: g_yT[kz][batch][gate] ----
        {
            float* y0 = g_yT + (size_t)kz * Bb * NN;
            int r0 = nt * 128 + wid * 16 + (lane >> 2);
            int c0 = 2 * (lane & 3);
#pragma unroll
            for (int nn = 0; nn < 4; nn++) {
                int col = nn * 8 + c0;
                y0[(size_t)col * NN + r0] = acc[nn][0];
                y0[(size_t)(col + 1) * NN + r0] = acc[nn][1];
                y0[(size_t)col * NN + r0 + 8] = acc[nn][2];
                y0[(size_t)(col + 1) * NN + r0 + 8] = acc[nn][3];
            }
        }
        grid_bar(NCTA * (2 * t + 1));

        // ---- epilogue on CTAs 0..31 (batch b) ----
        if (c < Bb) {
            const float* y0 = g_yT + (size_t)b * NN;
            const float* y1 = g_yT + (size_t)(Bb + b) * NN;
            float cpart = 0.f;
#pragma unroll
            for (int k = 0; k < 4; k++) {
                int j = tid + 256 * k;
                float gir = y0[j] + y1[j];
                float giz = y0[1024 + j] + y1[1024 + j];
                float gin = y0[2048 + j] + y1[2048 + j];
                float ghr = y0[3072 + j] + y1[3072 + j];
                float ghz = y0[4096 + j] + y1[4096 + j];
                float ghn = y0[5120 + j] + y1[5120 + j];
                float r = 1.f / (1.f + expf(-(gir + ghr + g_bias[j] + g_bias[3072 + j])));
                float z = 1.f / (1.f + expf(-(giz + ghz + g_bias[1024 + j] + g_bias[4096 + j])));
                float nv = tanhf(gin + g_bias[2048 + j] + r * (ghn + g_bias[5120 + j]));
                float hold = g_h[b * Hh + j];
                float hnew = (1.f - z) * nv + z * hold;
                g_h[b * Hh + j] = hnew;
                // repack h fragments for next step
                __nv_bfloat16 hi, lo;
                bsplit(hnew, hi, lo);
                int kz2;
                uint32_t off = bfr_off(j, b, kz2);
                char* ph = g_bfr + 131072 + kz2 * 65536;
                *(unsigned short*)(ph + off) = __bfloat16_as_ushort(hi);
                *(unsigned short*)(ph + 32768 + off) = __bfloat16_as_ushort(lo);
                cpart = fmaf(g_v1[j], hnew, cpart);
            }
            red[tid] = cpart;
            __syncthreads();
            for (int st = 128; st >= 1; st >>= 1) {
                if (tid < st) red[tid] += red[tid + st];
                __syncthreads();
            }
            float c0 = red[0];

            float s0 = tanhf(c0 + g_a[b * Ss + tid]);
            float s1 = tanhf(c0 + g_a[b * Ss + tid + 256]);
            float* pr = probs + ((size_t)b * Tt + t) * Ss;
            pr[tid] = s0;
            pr[tid + 256] = s1;
            float m0 = s0 + mask[b * Ss + tid];
            float m1 = s1 + mask[b * Ss + tid + 256];
            float bv = m0;
            int bi = tid;
            if (m1 > bv) { bv = m1; bi = tid + 256; }
            sv[tid] = bv;
            si[tid] = bi;
            __syncthreads();
            for (int st = 128; st >= 1; st >>= 1) {
                if (tid < st) {
                    float v = sv[tid + st];
                    int ii = si[tid + st];
                    if (v > sv[tid] || (v == sv[tid] && ii < si[tid])) { sv[tid] = v; si[tid] = ii; }
                }
                __syncthreads();
            }
            int idx = si[0];
            const float* xr = inputs + ((size_t)b * Ss + idx) * Hh;
#pragma unroll
            for (int k = 0; k < 4; k++) {
                int j = tid + 256 * k;
                float xv = xr[j];
                __nv_bfloat16 hi, lo;
                bsplit(xv, hi, lo);
                int kz2;
                uint32_t off = bfr_off(j, b, kz2);
                char* px = g_bfr + kz2 * 65536;
                *(unsigned short*)(px + off) = __bfloat16_as_ushort(hi);
                *(unsigned short*)(px + 32768 + off) = __bfloat16_as_ushort(lo);
            }
        }
        grid_bar(NCTA * (2 * t + 2));
    }
}

// ===================== context (step-0 softmax) =====================
__global__ void __launch_bounds__(256) ctx_kernel(const float* __restrict__ inputs,
                                                  const float* __restrict__ mask,
                                                  const float* __restrict__ probs,
                                                  float* __restrict__ ctx) {
    const int b = blockIdx.x;
    const int hq = blockIdx.y;
    const int tid = threadIdx.x;
    __shared__ float p[Ss];
    __shared__ float red[256];

    for (int s = tid; s < Ss; s += 256)
        p[s] = probs[(size_t)b * Tt * Ss + s] + mask[b * Ss + s];
    __syncthreads();
    float m = -1e30f;
    for (int s = tid; s < Ss; s += 256) m = fmaxf(m, p[s]);
    red[tid] = m;
    __syncthreads();
    for (int st = 128; st >= 1; st >>= 1) {
        if (tid < st) red[tid] = fmaxf(red[tid], red[tid + st]);
        __syncthreads();
    }
    const float mx = red[0];
    __syncthreads();
    float sm = 0.f;
    for (int s = tid; s < Ss; s += 256) {
        float e = expf(p[s] - mx);
        p[s] = e;
        sm += e;
    }
    red[tid] = sm;
    __syncthreads();
    for (int st = 128; st >= 1; st >>= 1) {
        if (tid < st) red[tid] += red[tid + st];
        __syncthreads();
    }
    const float Z = red[0];
    __syncthreads();
    const int h = hq * 256 + tid;
    float acc = 0.f;
    for (int s = 0; s < Ss; s++)
        acc = fmaf(p[s], inputs[((size_t)b * Ss + s) * Hh + h], acc);
    ctx[b * Hh + h] = acc / Z;
}

// ===================== launch =====================
extern "C" void kernel_launch(void* const* d_in, const int* in_sizes, int n_in,
                              void* d_out, int out_size) {
    const float* inputs   = (const float*)d_in[0];
    const float* mask     = (const float*)d_in[1];
    // d_in[2] = inputs_embeds (unused, use_emb=False)
    const float* features = (const float*)d_in[3];
    const float* w_ih     = (const float*)d_in[4];
    const float* b_ih     = (const float*)d_in[5];
    const float* w_hh     = (const float*)d_in[6];
    const float* b_hh     = (const float*)d_in[7];
    const float* W1       = (const float*)d_in[8];
    const float* W2       = (const float*)d_in[9];
    const float* V        = (const float*)d_in[10];

    float* out   = (float*)d_out;
    float* probs = out;                            // [B, T, S]
    float* ctx   = out + (size_t)Bb * Tt * Ss;     // [B, H]

    cudaFuncSetAttribute(gru_persist, cudaFuncAttributeMaxDynamicSharedMemorySize, DSMEM);

    prep_pack_b<<<Bb, 256>>>(features);
    prep_v<<<8, 256>>>(W1, W2, V);
    prep_wfr<<<3072, 256>>>(w_ih, w_hh);
    prep_bias<<<NN / 1024, 1024>>>(b_ih, b_hh);
    prep_a<<<(Bb * Ss) / 8, 256>>>(inputs);

    gru_persist<<<NCTA, 256, DSMEM>>>(inputs, mask, probs);

    ctx_kernel<<<dim3(Bb, 4), 256>>>(inputs, mask, probs, ctx);
}